// round 16
// baseline (speedup 1.0000x reference)
#include <cuda_runtime.h>
#include <cstdint>

// LIF-MC-Refrac (R16):
//  K_reset : zero suspect counter.
//  K_mma   : 1024 CTAs. bid<512 -> coupling (single-pass RNA-tf32 MMA,
//            double-buffered) -> z,v,rho + suspect flags.
//            bid>=512 -> i-path TF32 MMA (double-buffered) -> i.
//            (independent data; packed into one launch to kill partial waves)
//  K_fixup : exact serial-k fp32 recompute of flagged elements (0-flip order).

namespace {
constexpr int Bd = 4096;
constexpr int Hd = 2048;
constexpr int Kd = 2048;

constexpr int BM = 128, BN = 128, BK = 16;
constexpr int SSTR = BK + 4;
constexpr int TILEW = BM * SSTR;        // words per tile buffer (2560)

constexpr float DT_TAU_MEM = 0.1f;
constexpr float DT_TAU_SYN = 0.2f;
constexpr float V_TH_C     = 1.0f;
constexpr float RHO_RST    = 5.0f;

constexpr float EPS_FIX    = 4e-3f;
constexpr int   MAX_SUSP   = 1 << 20;

constexpr int CPL_BLKS = 512;
}

__device__ int g_susp_count;
__device__ int g_susp_list[MAX_SUSP];

__device__ __forceinline__ uint32_t f2tf32(float x) {
    uint32_t r;
    asm("cvt.rna.tf32.f32 %0, %1;" : "=r"(r) : "f"(x));
    return r;
}

__device__ __forceinline__ void mma_tf32(float& c0, float& c1, float& c2, float& c3,
                                         uint32_t a0, uint32_t a1, uint32_t a2, uint32_t a3,
                                         uint32_t b0, uint32_t b1)
{
    asm volatile(
        "mma.sync.aligned.m16n8k8.row.col.f32.tf32.tf32.f32 "
        "{%0,%1,%2,%3},{%4,%5,%6,%7},{%8,%9},{%0,%1,%2,%3};"
        : "+f"(c0), "+f"(c1), "+f"(c2), "+f"(c3)
        : "r"(a0), "r"(a1), "r"(a2), "r"(a3), "r"(b0), "r"(b1));
}

__device__ __forceinline__ void lif_elem(float v, float i, float rho, float couple,
                                         float& z_out, float& v_out, float& rho_out)
{
    float dv    = DT_TAU_MEM * ((0.0f - v) + i);
    float v_dec = (v + dv) + couple;
    float z     = (v_dec - V_TH_C) > 0.0f ? 1.0f : 0.0f;
    float v_new = (1.0f - z) * v_dec;
    float mask  = rho > 0.0f ? 1.0f : 0.0f;
    v_new = (1.0f - mask) * v_new + mask * v;
    z     = (1.0f - mask) * z;
    rho_out = (1.0f - z) * fmaxf(rho - mask, 0.0f) + z * RHO_RST;
    z_out = z;
    v_out = v_new;
}

// =============== K_reset ======================================================
__global__ void reset_kernel() {
    if (threadIdx.x == 0) g_susp_count = 0;
}

// =============== K_mma: coupling (bid<512) + i-path (bid>=512) ===============
__global__ void __launch_bounds__(256, 2) mma_kernel(
    const float* __restrict__ inp, const float* __restrict__ zin,
    const float* __restrict__ vin, const float* __restrict__ iin,
    const float* __restrict__ rhoin,
    const float* __restrict__ Wi,  const float* __restrict__ Wr,
    const float* __restrict__ gmat,
    float* __restrict__ out_z, float* __restrict__ out_v,
    float* __restrict__ out_i, float* __restrict__ out_rho)
{
    __shared__ uint32_t Ahi[2 * TILEW];
    __shared__ uint32_t Bhi[2 * TILEW];

    const int bid  = blockIdx.x;
    const int role = (bid < CPL_BLKS) ? 0 : 1;   // 0 = coupling, 1 = i-path
    const int sub  = role ? (bid - CPL_BLKS) : bid;
    const int bx = sub & 15;
    const int by = sub >> 4;

    const int tid  = threadIdx.x;
    const int warp = tid >> 5;
    const int lane = tid & 31;
    const int g    = lane >> 2;
    const int q    = lane & 3;
    const int wM   = warp >> 2;
    const int wN   = warp & 3;

    const int loadRow = tid >> 2;
    const int loadK   = (tid & 3) << 2;
    const int t       = tid & 3;
    const int ta_     = t >> 1;
    const int tb_     = t & 1;

    const int d0 = (ta_ ? 10 : 0) + tb_;
    const int d1 = (ta_ ? 14 : 4) + tb_;
    const int d2 = (ta_ ?  8 : 2) + tb_;
    const int d3 = (ta_ ? 12 : 6) + tb_;

    const int B0q  = ((q & 1) << 2) | (q & 2);
    const int off0 = B0q;
    const int off1 = 8 + (B0q ^ 2);

    const int r0s = loadRow * SSTR;
    const int r1s = (loadRow + 64) * SSTR;

    float acc[4][4][4];
#pragma unroll
    for (int mt = 0; mt < 4; ++mt)
#pragma unroll
        for (int nt = 0; nt < 4; ++nt)
#pragma unroll
            for (int r = 0; r < 4; ++r) acc[mt][nt][r] = 0.0f;

    const int NPASS = role ? 2 : 1;
    for (int p = 0; p < NPASS; ++p) {
        const float* Amat = role ? (p == 0 ? inp : zin) : vin;
        const float* Wmat = role ? (p == 0 ? Wi  : Wr ) : gmat;
        const float* aPtr = Amat + (size_t)(by * BM + loadRow) * Kd + loadK;
        const float* wPtr = Wmat + (size_t)(bx * BN + loadRow) * Kd + loadK;

        float4 ra0 = *(const float4*)(aPtr);
        float4 ra1 = *(const float4*)(aPtr + (size_t)64 * Kd);
        float4 rb0 = *(const float4*)(wPtr);
        float4 rb1 = *(const float4*)(wPtr + (size_t)64 * Kd);

        for (int kt = 0, j = 0; kt < Kd; kt += BK, ++j) {
            uint32_t* Ab = Ahi + (j & 1) * TILEW;
            uint32_t* Bb = Bhi + (j & 1) * TILEW;

            if (role == 0) {
                // RNA tf32 conversion (coupling accuracy path)
                Ab[r0s + d0] = f2tf32(ra0.x);
                Ab[r0s + d1] = f2tf32(ra0.y);
                Ab[r0s + d2] = f2tf32(ra0.z);
                Ab[r0s + d3] = f2tf32(ra0.w);
                Ab[r1s + d0] = f2tf32(ra1.x);
                Ab[r1s + d1] = f2tf32(ra1.y);
                Ab[r1s + d2] = f2tf32(ra1.z);
                Ab[r1s + d3] = f2tf32(ra1.w);
                Bb[r0s + d0] = f2tf32(rb0.x);
                Bb[r0s + d1] = f2tf32(rb0.y);
                Bb[r0s + d2] = f2tf32(rb0.z);
                Bb[r0s + d3] = f2tf32(rb0.w);
                Bb[r1s + d0] = f2tf32(rb1.x);
                Bb[r1s + d1] = f2tf32(rb1.y);
                Bb[r1s + d2] = f2tf32(rb1.z);
                Bb[r1s + d3] = f2tf32(rb1.w);
            } else {
                // raw fp32 bits -> tf32 truncation (i-path tolerance)
                Ab[r0s + d0] = __float_as_uint(ra0.x);
                Ab[r0s + d1] = __float_as_uint(ra0.y);
                Ab[r0s + d2] = __float_as_uint(ra0.z);
                Ab[r0s + d3] = __float_as_uint(ra0.w);
                Ab[r1s + d0] = __float_as_uint(ra1.x);
                Ab[r1s + d1] = __float_as_uint(ra1.y);
                Ab[r1s + d2] = __float_as_uint(ra1.z);
                Ab[r1s + d3] = __float_as_uint(ra1.w);
                Bb[r0s + d0] = __float_as_uint(rb0.x);
                Bb[r0s + d1] = __float_as_uint(rb0.y);
                Bb[r0s + d2] = __float_as_uint(rb0.z);
                Bb[r0s + d3] = __float_as_uint(rb0.w);
                Bb[r1s + d0] = __float_as_uint(rb1.x);
                Bb[r1s + d1] = __float_as_uint(rb1.y);
                Bb[r1s + d2] = __float_as_uint(rb1.z);
                Bb[r1s + d3] = __float_as_uint(rb1.w);
            }
            __syncthreads();

            if (kt + BK < Kd) {
                aPtr += BK; wPtr += BK;
                ra0 = *(const float4*)(aPtr);
                ra1 = *(const float4*)(aPtr + (size_t)64 * Kd);
                rb0 = *(const float4*)(wPtr);
                rb1 = *(const float4*)(wPtr + (size_t)64 * Kd);
            }

#pragma unroll
            for (int ks = 0; ks < 2; ++ks) {
                const int kb = ks ? off1 : off0;
                uint2 bh[4];
#pragma unroll
                for (int nt = 0; nt < 4; ++nt)
                    bh[nt] = *(const uint2*)&Bb[(wN * 32 + nt * 8 + g) * SSTR + kb];
#pragma unroll
                for (int mt = 0; mt < 4; ++mt) {
                    const int r0 = (wM * 64 + mt * 16 + g) * SSTR + kb;
                    uint2 tA = *(const uint2*)&Ab[r0];
                    uint2 tC = *(const uint2*)&Ab[r0 + 8 * SSTR];
#pragma unroll
                    for (int nt = 0; nt < 4; ++nt) {
                        float* c = acc[mt][nt];
                        mma_tf32(c[0], c[1], c[2], c[3],
                                 tA.x, tC.x, tA.y, tC.y, bh[nt].x, bh[nt].y);
                    }
                }
            }
        }
        // cross-p buffer hazard: next p's first STS hits buffer 0, whose last
        // reads were tile 126 (fenced by tile 127's sync). Safe without extra sync.
    }

    // ---- epilogues ----
#pragma unroll
    for (int mt = 0; mt < 4; ++mt) {
#pragma unroll
        for (int nt = 0; nt < 4; ++nt) {
            const float* c = acc[mt][nt];
            const int row0 = by * BM + wM * 64 + mt * 16 + g;
            const int col  = bx * BN + wN * 32 + nt * 8 + 2 * q;

            if (role == 1) {
                const size_t idx0 = (size_t)row0 * Hd + col;
                const size_t idx1 = idx0 + (size_t)8 * Hd;
                float2 i0 = *(const float2*)(iin + idx0);
                float2 i1 = *(const float2*)(iin + idx1);
                float2 o0, o1;
                o0.x = (i0.x - DT_TAU_SYN * i0.x) + c[0];
                o0.y = (i0.y - DT_TAU_SYN * i0.y) + c[1];
                o1.x = (i1.x - DT_TAU_SYN * i1.x) + c[2];
                o1.y = (i1.y - DT_TAU_SYN * i1.y) + c[3];
                *(float2*)(out_i + idx0) = o0;
                *(float2*)(out_i + idx1) = o1;
            } else {
#pragma unroll
                for (int h = 0; h < 2; ++h) {
                    const int row = row0 + 8 * h;
                    const size_t idx = (size_t)row * Hd + col;
                    float2 vv = *(const float2*)(vin + idx);
                    float2 iv = *(const float2*)(iin + idx);
                    float2 rv = *(const float2*)(rhoin + idx);
                    float2 oz, ov, orh;
                    lif_elem(vv.x, iv.x, rv.x, c[2 * h + 0], oz.x, ov.x, orh.x);
                    lif_elem(vv.y, iv.y, rv.y, c[2 * h + 1], oz.y, ov.y, orh.y);
                    *(float2*)(out_z   + idx) = oz;
                    *(float2*)(out_v   + idx) = ov;
                    *(float2*)(out_rho + idx) = orh;

                    float vd0 = (vv.x + DT_TAU_MEM * ((0.0f - vv.x) + iv.x)) + c[2 * h + 0];
                    float vd1 = (vv.y + DT_TAU_MEM * ((0.0f - vv.y) + iv.y)) + c[2 * h + 1];
                    if (fabsf(vd0 - V_TH_C) < EPS_FIX) {
                        int s = atomicAdd(&g_susp_count, 1);
                        if (s < MAX_SUSP) g_susp_list[s] = (int)idx;
                    }
                    if (fabsf(vd1 - V_TH_C) < EPS_FIX) {
                        int s = atomicAdd(&g_susp_count, 1);
                        if (s < MAX_SUSP) g_susp_list[s] = (int)(idx + 1);
                    }
                }
            }
        }
    }
}

// =============== K_fixup: exact recompute of flagged elements ================
__global__ void __launch_bounds__(256) fixup_kernel(
    const float* __restrict__ vin, const float* __restrict__ gmat,
    const float* __restrict__ iin, const float* __restrict__ rhoin,
    float* __restrict__ out_z, float* __restrict__ out_v, float* __restrict__ out_rho)
{
    int n = g_susp_count;
    if (n > MAX_SUSP) n = MAX_SUSP;
    for (int s = blockIdx.x * blockDim.x + threadIdx.x; s < n;
         s += gridDim.x * blockDim.x) {
        const int e   = g_susp_list[s];
        const int row = e >> 11;       // Hd = 2048
        const int col = e & 2047;

        const float4* ar = (const float4*)(vin  + (size_t)row * Kd);
        const float4* br = (const float4*)(gmat + (size_t)col * Kd);
        float accv = 0.0f;
#pragma unroll 8
        for (int k4 = 0; k4 < Kd / 4; ++k4) {
            float4 a = ar[k4];
            float4 b = br[k4];
            accv = fmaf(a.x, b.x, accv);
            accv = fmaf(a.y, b.y, accv);
            accv = fmaf(a.z, b.z, accv);
            accv = fmaf(a.w, b.w, accv);
        }

        const size_t idx = (size_t)row * Hd + col;
        float z, vo, ro;
        lif_elem(vin[idx], iin[idx], rhoin[idx], accv, z, vo, ro);
        out_z[idx]   = z;
        out_v[idx]   = vo;
        out_rho[idx] = ro;
    }
}

extern "C" void kernel_launch(void* const* d_in, const int* in_sizes, int n_in,
                              void* d_out, int out_size)
{
    const float* inp  = (const float*)d_in[0];
    const float* z    = (const float*)d_in[1];
    const float* v    = (const float*)d_in[2];
    const float* icur = (const float*)d_in[3];
    const float* rho  = (const float*)d_in[4];
    const float* Wi   = (const float*)d_in[5];
    const float* Wr   = (const float*)d_in[6];
    const float* g    = (const float*)d_in[7];

    float* out      = (float*)d_out;
    const size_t nBH = (size_t)Bd * Hd;
    float* out_z    = out;
    float* out_v    = out + nBH;
    float* out_i    = out + 2 * nBH;
    float* out_rho  = out + 3 * nBH;

    reset_kernel<<<1, 32>>>();
    mma_kernel<<<1024, 256>>>(inp, z, v, icur, rho, Wi, Wr, g,
                              out_z, out_v, out_i, out_rho);
    fixup_kernel<<<64, 256>>>(v, g, icur, rho, out_z, out_v, out_rho);
}

// round 17
// speedup vs baseline: 1.1388x; 1.1388x over previous
#include <cuda_runtime.h>
#include <cstdint>

// LIF-MC-Refrac (R17):
//  K_reset : zero suspect counter.
//  K_mma   : 1024 CTAs x 128 thr, warp tile 64x64 (4 warps -> CTA 128x128),
//            double-buffered smem, R11 conflict-free k-position map.
//            bid<512 -> coupling (RNA-tf32, 1 pass) -> z,v,rho + suspect flags
//            bid>=512 -> i-path (trunc-tf32, 2 passes) -> i
//  K_fixup : exact serial-k fp32 recompute of flagged elements (0-flip order).

namespace {
constexpr int Bd = 4096;
constexpr int Hd = 2048;
constexpr int Kd = 2048;

constexpr int BM = 128, BN = 128, BK = 16;
constexpr int SSTR = BK + 4;            // 20 words
constexpr int TILEW = BM * SSTR;        // 2560 words per tile buffer

constexpr float DT_TAU_MEM = 0.1f;
constexpr float DT_TAU_SYN = 0.2f;
constexpr float V_TH_C     = 1.0f;
constexpr float RHO_RST    = 5.0f;

constexpr float EPS_FIX    = 4e-3f;
constexpr int   MAX_SUSP   = 1 << 20;

constexpr int CPL_BLKS = 512;
}

__device__ int g_susp_count;
__device__ int g_susp_list[MAX_SUSP];

__device__ __forceinline__ uint32_t f2tf32(float x) {
    uint32_t r;
    asm("cvt.rna.tf32.f32 %0, %1;" : "=r"(r) : "f"(x));
    return r;
}

__device__ __forceinline__ void mma_tf32(float& c0, float& c1, float& c2, float& c3,
                                         uint32_t a0, uint32_t a1, uint32_t a2, uint32_t a3,
                                         uint32_t b0, uint32_t b1)
{
    asm volatile(
        "mma.sync.aligned.m16n8k8.row.col.f32.tf32.tf32.f32 "
        "{%0,%1,%2,%3},{%4,%5,%6,%7},{%8,%9},{%0,%1,%2,%3};"
        : "+f"(c0), "+f"(c1), "+f"(c2), "+f"(c3)
        : "r"(a0), "r"(a1), "r"(a2), "r"(a3), "r"(b0), "r"(b1));
}

__device__ __forceinline__ void lif_elem(float v, float i, float rho, float couple,
                                         float& z_out, float& v_out, float& rho_out)
{
    float dv    = DT_TAU_MEM * ((0.0f - v) + i);
    float v_dec = (v + dv) + couple;
    float z     = (v_dec - V_TH_C) > 0.0f ? 1.0f : 0.0f;
    float v_new = (1.0f - z) * v_dec;
    float mask  = rho > 0.0f ? 1.0f : 0.0f;
    v_new = (1.0f - mask) * v_new + mask * v;
    z     = (1.0f - mask) * z;
    rho_out = (1.0f - z) * fmaxf(rho - mask, 0.0f) + z * RHO_RST;
    z_out = z;
    v_out = v_new;
}

// =============== K_reset ======================================================
__global__ void reset_kernel() {
    if (threadIdx.x == 0) g_susp_count = 0;
}

// =============== K_mma: 128 thr, 64x64 warp tiles, double-buffered ===========
__global__ void __launch_bounds__(128, 2) mma_kernel(
    const float* __restrict__ inp, const float* __restrict__ zin,
    const float* __restrict__ vin, const float* __restrict__ iin,
    const float* __restrict__ rhoin,
    const float* __restrict__ Wi,  const float* __restrict__ Wr,
    const float* __restrict__ gmat,
    float* __restrict__ out_z, float* __restrict__ out_v,
    float* __restrict__ out_i, float* __restrict__ out_rho)
{
    __shared__ uint32_t Ahi[2 * TILEW];
    __shared__ uint32_t Bhi[2 * TILEW];

    const int bid  = blockIdx.x;
    const int role = (bid < CPL_BLKS) ? 0 : 1;   // 0 = coupling, 1 = i-path
    const int sub  = role ? (bid - CPL_BLKS) : bid;
    const int bx = sub & 15;
    const int by = sub >> 4;

    const int tid  = threadIdx.x;
    const int warp = tid >> 5;
    const int lane = tid & 31;
    const int g    = lane >> 2;
    const int q    = lane & 3;
    const int wM   = warp >> 1;         // 0..1 -> 64 rows
    const int wN   = warp & 1;          // 0..1 -> 64 cols

    const int loadRow = tid >> 2;       // 0..31; rows {r, r+32, r+64, r+96}
    const int loadK   = (tid & 3) << 2;
    const int t       = tid & 3;
    const int ta_     = t >> 1;
    const int tb_     = t & 1;

    // R11 position map: pos(k)=2f(a,c)+b, f0=[0,2,1,3], f1=[5,7,4,6]
    const int d0 = (ta_ ? 10 : 0) + tb_;
    const int d1 = (ta_ ? 14 : 4) + tb_;
    const int d2 = (ta_ ?  8 : 2) + tb_;
    const int d3 = (ta_ ? 12 : 6) + tb_;

    const int B0q  = ((q & 1) << 2) | (q & 2);
    const int off0 = B0q;
    const int off1 = 8 + (B0q ^ 2);

    float acc[4][8][4];                 // warp tile 64x64
#pragma unroll
    for (int mt = 0; mt < 4; ++mt)
#pragma unroll
        for (int nt = 0; nt < 8; ++nt)
#pragma unroll
            for (int r = 0; r < 4; ++r) acc[mt][nt][r] = 0.0f;

    const int NPASS = role ? 2 : 1;
    for (int p = 0; p < NPASS; ++p) {
        const float* Amat = role ? (p == 0 ? inp : zin) : vin;
        const float* Wmat = role ? (p == 0 ? Wi  : Wr ) : gmat;
        const float* aPtr = Amat + (size_t)(by * BM + loadRow) * Kd + loadK;
        const float* wPtr = Wmat + (size_t)(bx * BN + loadRow) * Kd + loadK;

        float4 ra[4], rb[4];
#pragma unroll
        for (int r = 0; r < 4; ++r) {
            ra[r] = *(const float4*)(aPtr + (size_t)(32 * r) * Kd);
            rb[r] = *(const float4*)(wPtr + (size_t)(32 * r) * Kd);
        }

        for (int kt = 0, j = 0; kt < Kd; kt += BK, ++j) {
            uint32_t* Ab = Ahi + (j & 1) * TILEW;
            uint32_t* Bb = Bhi + (j & 1) * TILEW;

#pragma unroll
            for (int r = 0; r < 4; ++r) {
                const int rr = (loadRow + 32 * r) * SSTR;
                if (role == 0) {
                    Ab[rr + d0] = f2tf32(ra[r].x);
                    Ab[rr + d1] = f2tf32(ra[r].y);
                    Ab[rr + d2] = f2tf32(ra[r].z);
                    Ab[rr + d3] = f2tf32(ra[r].w);
                    Bb[rr + d0] = f2tf32(rb[r].x);
                    Bb[rr + d1] = f2tf32(rb[r].y);
                    Bb[rr + d2] = f2tf32(rb[r].z);
                    Bb[rr + d3] = f2tf32(rb[r].w);
                } else {
                    Ab[rr + d0] = __float_as_uint(ra[r].x);
                    Ab[rr + d1] = __float_as_uint(ra[r].y);
                    Ab[rr + d2] = __float_as_uint(ra[r].z);
                    Ab[rr + d3] = __float_as_uint(ra[r].w);
                    Bb[rr + d0] = __float_as_uint(rb[r].x);
                    Bb[rr + d1] = __float_as_uint(rb[r].y);
                    Bb[rr + d2] = __float_as_uint(rb[r].z);
                    Bb[rr + d3] = __float_as_uint(rb[r].w);
                }
            }
            __syncthreads();

            if (kt + BK < Kd) {
                aPtr += BK; wPtr += BK;
#pragma unroll
                for (int r = 0; r < 4; ++r) {
                    ra[r] = *(const float4*)(aPtr + (size_t)(32 * r) * Kd);
                    rb[r] = *(const float4*)(wPtr + (size_t)(32 * r) * Kd);
                }
            }

#pragma unroll
            for (int ks = 0; ks < 2; ++ks) {
                const int kb = ks ? off1 : off0;
                uint2 bq[8];
#pragma unroll
                for (int nt = 0; nt < 8; ++nt)
                    bq[nt] = *(const uint2*)&Bb[(wN * 64 + nt * 8 + g) * SSTR + kb];
#pragma unroll
                for (int mt = 0; mt < 4; ++mt) {
                    const int r0 = (wM * 64 + mt * 16 + g) * SSTR + kb;
                    uint2 tA = *(const uint2*)&Ab[r0];
                    uint2 tC = *(const uint2*)&Ab[r0 + 8 * SSTR];
#pragma unroll
                    for (int nt = 0; nt < 8; ++nt) {
                        float* c = acc[mt][nt];
                        mma_tf32(c[0], c[1], c[2], c[3],
                                 tA.x, tC.x, tA.y, tC.y, bq[nt].x, bq[nt].y);
                    }
                }
            }
        }
        // cross-p hazard: next p's first STS hits buffer 0; its last reads were
        // tile 126, fenced by tile 127's sync. Safe.
    }

    // ---- epilogues ----
#pragma unroll
    for (int mt = 0; mt < 4; ++mt) {
#pragma unroll
        for (int nt = 0; nt < 8; ++nt) {
            const float* c = acc[mt][nt];
            const int row0 = by * BM + wM * 64 + mt * 16 + g;
            const int col  = bx * BN + wN * 64 + nt * 8 + 2 * q;

            if (role == 1) {
                const size_t idx0 = (size_t)row0 * Hd + col;
                const size_t idx1 = idx0 + (size_t)8 * Hd;
                float2 i0 = *(const float2*)(iin + idx0);
                float2 i1 = *(const float2*)(iin + idx1);
                float2 o0, o1;
                o0.x = (i0.x - DT_TAU_SYN * i0.x) + c[0];
                o0.y = (i0.y - DT_TAU_SYN * i0.y) + c[1];
                o1.x = (i1.x - DT_TAU_SYN * i1.x) + c[2];
                o1.y = (i1.y - DT_TAU_SYN * i1.y) + c[3];
                *(float2*)(out_i + idx0) = o0;
                *(float2*)(out_i + idx1) = o1;
            } else {
#pragma unroll
                for (int h = 0; h < 2; ++h) {
                    const int row = row0 + 8 * h;
                    const size_t idx = (size_t)row * Hd + col;
                    float2 vv = *(const float2*)(vin + idx);
                    float2 iv = *(const float2*)(iin + idx);
                    float2 rv = *(const float2*)(rhoin + idx);
                    float2 oz, ov, orh;
                    lif_elem(vv.x, iv.x, rv.x, c[2 * h + 0], oz.x, ov.x, orh.x);
                    lif_elem(vv.y, iv.y, rv.y, c[2 * h + 1], oz.y, ov.y, orh.y);
                    *(float2*)(out_z   + idx) = oz;
                    *(float2*)(out_v   + idx) = ov;
                    *(float2*)(out_rho + idx) = orh;

                    float vd0 = (vv.x + DT_TAU_MEM * ((0.0f - vv.x) + iv.x)) + c[2 * h + 0];
                    float vd1 = (vv.y + DT_TAU_MEM * ((0.0f - vv.y) + iv.y)) + c[2 * h + 1];
                    if (fabsf(vd0 - V_TH_C) < EPS_FIX) {
                        int s = atomicAdd(&g_susp_count, 1);
                        if (s < MAX_SUSP) g_susp_list[s] = (int)idx;
                    }
                    if (fabsf(vd1 - V_TH_C) < EPS_FIX) {
                        int s = atomicAdd(&g_susp_count, 1);
                        if (s < MAX_SUSP) g_susp_list[s] = (int)(idx + 1);
                    }
                }
            }
        }
    }
}

// =============== K_fixup: exact recompute of flagged elements ================
__global__ void __launch_bounds__(256) fixup_kernel(
    const float* __restrict__ vin, const float* __restrict__ gmat,
    const float* __restrict__ iin, const float* __restrict__ rhoin,
    float* __restrict__ out_z, float* __restrict__ out_v, float* __restrict__ out_rho)
{
    int n = g_susp_count;
    if (n > MAX_SUSP) n = MAX_SUSP;
    for (int s = blockIdx.x * blockDim.x + threadIdx.x; s < n;
         s += gridDim.x * blockDim.x) {
        const int e   = g_susp_list[s];
        const int row = e >> 11;       // Hd = 2048
        const int col = e & 2047;

        const float4* ar = (const float4*)(vin  + (size_t)row * Kd);
        const float4* br = (const float4*)(gmat + (size_t)col * Kd);
        float accv = 0.0f;
#pragma unroll 8
        for (int k4 = 0; k4 < Kd / 4; ++k4) {
            float4 a = ar[k4];
            float4 b = br[k4];
            accv = fmaf(a.x, b.x, accv);
            accv = fmaf(a.y, b.y, accv);
            accv = fmaf(a.z, b.z, accv);
            accv = fmaf(a.w, b.w, accv);
        }

        const size_t idx = (size_t)row * Hd + col;
        float z, vo, ro;
        lif_elem(vin[idx], iin[idx], rhoin[idx], accv, z, vo, ro);
        out_z[idx]   = z;
        out_v[idx]   = vo;
        out_rho[idx] = ro;
    }
}

extern "C" void kernel_launch(void* const* d_in, const int* in_sizes, int n_in,
                              void* d_out, int out_size)
{
    const float* inp  = (const float*)d_in[0];
    const float* z    = (const float*)d_in[1];
    const float* v    = (const float*)d_in[2];
    const float* icur = (const float*)d_in[3];
    const float* rho  = (const float*)d_in[4];
    const float* Wi   = (const float*)d_in[5];
    const float* Wr   = (const float*)d_in[6];
    const float* g    = (const float*)d_in[7];

    float* out      = (float*)d_out;
    const size_t nBH = (size_t)Bd * Hd;
    float* out_z    = out;
    float* out_v    = out + nBH;
    float* out_i    = out + 2 * nBH;
    float* out_rho  = out + 3 * nBH;

    reset_kernel<<<1, 32>>>();
    mma_kernel<<<1024, 128>>>(inp, z, v, icur, rho, Wi, Wr, g,
                              out_z, out_v, out_i, out_rho);
    fixup_kernel<<<64, 256>>>(v, g, icur, rho, out_z, out_v, out_rho);
}